// round 3
// baseline (speedup 1.0000x reference)
#include <cuda_runtime.h>

#define D     128
#define NMAX  50000
#define EMAX  600000
#define GMAX  64
#define CHUNK 256
#define NCHUNKS ((NMAX + CHUNK - 1) / CHUNK)   // 196

// ---------------- device scratch (static: no allocation allowed) -------------
__device__ float g_x1[NMAX * D];
__device__ float g_x2[NMAX * D];
__device__ float g_ns[NMAX];
__device__ float g_nd[NMAX];
__device__ float g_cnt[GMAX];
__device__ int   g_ideg[NMAX];
__device__ int   g_row_start[NMAX + 1];
__device__ int   g_cursor[NMAX];
__device__ int   g_col[EMAX];
__device__ int   g_chunk[NCHUNKS];

// ---------------- helpers ----------------------------------------------------
__device__ __forceinline__ void redv4(float* p, float4 v) {
    asm volatile(
        "{\n\t"
        ".reg .u64 gp;\n\t"
        "cvta.to.global.u64 gp, %0;\n\t"
        "red.global.add.v4.f32 [gp], {%1, %2, %3, %4};\n\t"
        "}"
        :: "l"(p), "f"(v.x), "f"(v.y), "f"(v.z), "f"(v.w)
        : "memory");
}

__device__ __forceinline__ unsigned long long pack2(float lo, float hi) {
    unsigned long long r;
    asm("mov.b64 %0, {%1, %2};" : "=l"(r) : "f"(lo), "f"(hi));
    return r;
}
__device__ __forceinline__ void unpack2(unsigned long long p, float& lo, float& hi) {
    asm("mov.b64 {%0, %1}, %2;" : "=f"(lo), "=f"(hi) : "l"(p));
}
__device__ __forceinline__ void ffma2(unsigned long long& acc,
                                      unsigned long long a, unsigned long long b) {
    asm("fma.rn.f32x2 %0, %1, %2, %0;" : "+l"(acc) : "l"(a), "l"(b));
}

// ---------------- trivial kernels --------------------------------------------
__global__ void k_zero_f(float* __restrict__ p, int n) {
    int i = blockIdx.x * blockDim.x + threadIdx.x;
    int stride = gridDim.x * blockDim.x;
    for (; i < n; i += stride) p[i] = 0.0f;
}
__global__ void k_zero_i(int* __restrict__ p, int n) {
    int i = blockIdx.x * blockDim.x + threadIdx.x;
    int stride = gridDim.x * blockDim.x;
    for (; i < n; i += stride) p[i] = 0;
}

__global__ void k_degree(const int* __restrict__ src,
                         const int* __restrict__ dst,
                         float* __restrict__ ds, float* __restrict__ dd,
                         int* __restrict__ ideg, int E) {
    int e = blockIdx.x * blockDim.x + threadIdx.x;
    if (e < E) {
        atomicAdd(&ds[src[e]], 1.0f);
        int d = dst[e];
        atomicAdd(&dd[d], 1.0f);
        atomicAdd(&ideg[d], 1);
    }
}

// degrees -> rsqrt(clip(deg,1)); also accumulate per-graph node counts
__global__ void k_norm_cnt(float* __restrict__ ns, float* __restrict__ nd, int N,
                           const int* __restrict__ gid, float* __restrict__ cnt) {
    int i = blockIdx.x * blockDim.x + threadIdx.x;
    if (i < N) {
        ns[i] = rsqrtf(fmaxf(ns[i], 1.0f));
        nd[i] = rsqrtf(fmaxf(nd[i], 1.0f));
        atomicAdd(&cnt[gid[i]], 1.0f);
    }
}

// ---------------- CSR build ---------------------------------------------------
// A: per-chunk sums of in-degree
__global__ void k_chunk_sum(const int* __restrict__ ideg, int* __restrict__ chunk, int N) {
    __shared__ int s[CHUNK];
    int i = blockIdx.x * CHUNK + threadIdx.x;
    s[threadIdx.x] = (i < N) ? ideg[i] : 0;
    __syncthreads();
    for (int off = CHUNK / 2; off > 0; off >>= 1) {
        if (threadIdx.x < off) s[threadIdx.x] += s[threadIdx.x + off];
        __syncthreads();
    }
    if (threadIdx.x == 0) chunk[blockIdx.x] = s[0];
}

// B: exclusive scan of chunk sums (single block)
__global__ void k_chunk_scan(int* __restrict__ chunk, int n) {
    __shared__ int s[CHUNK];
    int tid = threadIdx.x;
    int v = (tid < n) ? chunk[tid] : 0;
    s[tid] = v;
    __syncthreads();
    for (int off = 1; off < CHUNK; off <<= 1) {
        int t = (tid >= off) ? s[tid - off] : 0;
        __syncthreads();
        s[tid] += t;
        __syncthreads();
    }
    if (tid < n) chunk[tid] = s[tid] - v;   // exclusive
}

// C: local exclusive scan per chunk + offset -> row_start, cursor
__global__ void k_row_start(const int* __restrict__ ideg, const int* __restrict__ chunk,
                            int* __restrict__ row_start, int* __restrict__ cursor,
                            int N, int E) {
    __shared__ int s[CHUNK];
    int tid = threadIdx.x;
    int i = blockIdx.x * CHUNK + tid;
    int v = (i < N) ? ideg[i] : 0;
    s[tid] = v;
    __syncthreads();
    for (int off = 1; off < CHUNK; off <<= 1) {
        int t = (tid >= off) ? s[tid - off] : 0;
        __syncthreads();
        s[tid] += t;
        __syncthreads();
    }
    if (i < N) {
        int rs = chunk[blockIdx.x] + s[tid] - v;
        row_start[i] = rs;
        cursor[i] = rs;
        if (i == N - 1) row_start[N] = E;
    }
}

// D: scatter edges into CSR
__global__ void k_fill(const int* __restrict__ src, const int* __restrict__ dst,
                       int* __restrict__ cursor, int* __restrict__ col, int E) {
    int e = blockIdx.x * blockDim.x + threadIdx.x;
    if (e < E) {
        int pos = atomicAdd(&cursor[dst[e]], 1);
        col[pos] = src[e];
    }
}

// ---------------- fused SpMM-gather + GEMM ------------------------------------
// y = relu((segment_sum(x[src]*ns[src] by dst) * nd[:,None]) @ W + b)
// Block: 64 rows x 128 cols, 256 threads; thread = 8 rows x 4 cols.
template <bool POOL>
__global__ __launch_bounds__(256)
void k_layer(const float* __restrict__ xin,
             const int* __restrict__ row_start, const int* __restrict__ col,
             const float* __restrict__ ns, const float* __restrict__ nd,
             const float* __restrict__ W, const float* __restrict__ b,
             float* __restrict__ y,
             const int* __restrict__ gid, float* __restrict__ gsum, int N) {
    __shared__ float Xs[64][D];

    int tid  = threadIdx.x;
    int tx   = tid & 31;   // lane: cols tx*4 .. tx*4+3
    int ty   = tid >> 5;   // warp: rows ty*8 .. ty*8+7
    int row0 = blockIdx.x * 64;

    const float4* x4 = (const float4*)xin;

    // --- gather phase: CSR in-edge accumulate per row ---
#pragma unroll
    for (int r = 0; r < 8; r++) {
        int rl  = ty * 8 + r;
        int row = row0 + rl;
        float4 a0 = make_float4(0.f, 0.f, 0.f, 0.f);
        float4 a1 = make_float4(0.f, 0.f, 0.f, 0.f);
        if (row < N) {
            int e0 = __ldg(&row_start[row]);
            int e1 = __ldg(&row_start[row + 1]);
            int e  = e0;
            for (; e + 1 < e1; e += 2) {
                int s0 = __ldg(&col[e]);
                int s1 = __ldg(&col[e + 1]);
                float c0 = __ldg(&ns[s0]);
                float c1 = __ldg(&ns[s1]);
                float4 v0 = __ldg(&x4[(size_t)s0 * 32 + tx]);
                float4 v1 = __ldg(&x4[(size_t)s1 * 32 + tx]);
                a0.x += v0.x * c0; a0.y += v0.y * c0; a0.z += v0.z * c0; a0.w += v0.w * c0;
                a1.x += v1.x * c1; a1.y += v1.y * c1; a1.z += v1.z * c1; a1.w += v1.w * c1;
            }
            if (e < e1) {
                int s0 = __ldg(&col[e]);
                float c0 = __ldg(&ns[s0]);
                float4 v0 = __ldg(&x4[(size_t)s0 * 32 + tx]);
                a0.x += v0.x * c0; a0.y += v0.y * c0; a0.z += v0.z * c0; a0.w += v0.w * c0;
            }
            float s = __ldg(&nd[row]);
            a0.x = (a0.x + a1.x) * s;
            a0.y = (a0.y + a1.y) * s;
            a0.z = (a0.z + a1.z) * s;
            a0.w = (a0.w + a1.w) * s;
        }
        *(float4*)&Xs[rl][tx * 4] = a0;
    }
    __syncthreads();

    // --- GEMM phase ---
    unsigned long long acc[8][2];
#pragma unroll
    for (int r = 0; r < 8; r++) { acc[r][0] = 0ull; acc[r][1] = 0ull; }

    const float4* W4 = (const float4*)W;
#pragma unroll 4
    for (int k = 0; k < 128; k++) {
        float4 w = __ldg(&W4[k * 32 + tx]);
        unsigned long long w01 = pack2(w.x, w.y);
        unsigned long long w23 = pack2(w.z, w.w);
#pragma unroll
        for (int r = 0; r < 8; r++) {
            float xv = Xs[ty * 8 + r][k];    // warp-uniform broadcast LDS
            unsigned long long xx = pack2(xv, xv);
            ffma2(acc[r][0], xx, w01);
            ffma2(acc[r][1], xx, w23);
        }
    }

    float4 bb = __ldg(((const float4*)b) + tx);

    if (!POOL) {
#pragma unroll
        for (int r = 0; r < 8; r++) {
            int row = row0 + ty * 8 + r;
            if (row < N) {
                float o0, o1, o2, o3;
                unpack2(acc[r][0], o0, o1);
                unpack2(acc[r][1], o2, o3);
                float4 o = make_float4(fmaxf(o0 + bb.x, 0.f), fmaxf(o1 + bb.y, 0.f),
                                       fmaxf(o2 + bb.z, 0.f), fmaxf(o3 + bb.w, 0.f));
                *(float4*)(y + (size_t)row * D + tx * 4) = o;
            }
        }
    } else {
        // fused per-graph sum: graph_ids sorted -> flush-on-change
        int cur = -1;
        float4 s4 = make_float4(0.f, 0.f, 0.f, 0.f);
#pragma unroll
        for (int r = 0; r < 8; r++) {
            int row = row0 + ty * 8 + r;
            if (row >= N) break;
            float o0, o1, o2, o3;
            unpack2(acc[r][0], o0, o1);
            unpack2(acc[r][1], o2, o3);
            float4 o = make_float4(fmaxf(o0 + bb.x, 0.f), fmaxf(o1 + bb.y, 0.f),
                                   fmaxf(o2 + bb.z, 0.f), fmaxf(o3 + bb.w, 0.f));
            int g = __ldg(&gid[row]);
            if (g != cur) {
                if (cur >= 0) redv4(gsum + (size_t)cur * D + tx * 4, s4);
                cur = g;
                s4 = o;
            } else {
                s4.x += o.x; s4.y += o.y; s4.z += o.z; s4.w += o.w;
            }
        }
        if (cur >= 0) redv4(gsum + (size_t)cur * D + tx * 4, s4);
    }
}

__global__ void k_final(float* __restrict__ out, const float* __restrict__ cnt, int n) {
    int i = blockIdx.x * blockDim.x + threadIdx.x;
    if (i < n) out[i] /= fmaxf(cnt[i >> 7], 1.0f);
}

// ---------------- launch ------------------------------------------------------
extern "C" void kernel_launch(void* const* d_in, const int* in_sizes, int n_in,
                              void* d_out, int out_size) {
    const float* h   = (const float*)d_in[0];
    const int*   src = (const int*)d_in[1];   // int32 (JAX x64 disabled)
    const int*   dst = (const int*)d_in[2];
    const int*   gid = (const int*)d_in[3];
    const float* W1 = (const float*)d_in[4];
    const float* b1 = (const float*)d_in[5];
    const float* W2 = (const float*)d_in[6];
    const float* b2 = (const float*)d_in[7];
    const float* W3 = (const float*)d_in[8];
    const float* b3 = (const float*)d_in[9];

    int N = in_sizes[0] / D;
    int E = in_sizes[1];
    float* out = (float*)d_out;

    float *x1, *x2, *ns, *nd, *cnt;
    int *ideg, *row_start, *cursor, *col, *chunk;
    cudaGetSymbolAddress((void**)&x1,  g_x1);
    cudaGetSymbolAddress((void**)&x2,  g_x2);
    cudaGetSymbolAddress((void**)&ns,  g_ns);
    cudaGetSymbolAddress((void**)&nd,  g_nd);
    cudaGetSymbolAddress((void**)&cnt, g_cnt);
    cudaGetSymbolAddress((void**)&ideg,      g_ideg);
    cudaGetSymbolAddress((void**)&row_start, g_row_start);
    cudaGetSymbolAddress((void**)&cursor,    g_cursor);
    cudaGetSymbolAddress((void**)&col,       g_col);
    cudaGetSymbolAddress((void**)&chunk,     g_chunk);

    int nchunks    = (N + CHUNK - 1) / CHUNK;
    int gemmBlocks = (N + 63) / 64;

    // init
    k_zero_f<<<128, 256>>>(ns, N);
    k_zero_f<<<128, 256>>>(nd, N);
    k_zero_i<<<128, 256>>>(ideg, N);
    k_zero_f<<<1, 64>>>(cnt, GMAX);
    k_zero_f<<<32, 256>>>(out, GMAX * D);

    // degrees + norms + graph counts
    k_degree<<<(E + 255) / 256, 256>>>(src, dst, ns, nd, ideg, E);
    k_norm_cnt<<<(N + 255) / 256, 256>>>(ns, nd, N, gid, cnt);

    // CSR build
    k_chunk_sum<<<nchunks, CHUNK>>>(ideg, chunk, N);
    k_chunk_scan<<<1, CHUNK>>>(chunk, nchunks);
    k_row_start<<<nchunks, CHUNK>>>(ideg, chunk, row_start, cursor, N, E);
    k_fill<<<(E + 255) / 256, 256>>>(src, dst, cursor, col, E);

    // layer 1: h -> x1
    k_layer<false><<<gemmBlocks, 256>>>(h, row_start, col, ns, nd, W1, b1, x1,
                                        nullptr, nullptr, N);
    // layer 2: x1 -> x2
    k_layer<false><<<gemmBlocks, 256>>>(x1, row_start, col, ns, nd, W2, b2, x2,
                                        nullptr, nullptr, N);
    // layer 3: x2 -> pooled sums into d_out
    k_layer<true><<<gemmBlocks, 256>>>(x2, row_start, col, ns, nd, W3, b3, nullptr,
                                       gid, out, N);

    // mean = sum / count
    k_final<<<(GMAX * D + 255) / 256, 256>>>(out, cnt, GMAX * D);
}

// round 4
// speedup vs baseline: 1.0698x; 1.0698x over previous
#include <cuda_runtime.h>

#define D     128
#define NMAX  50000
#define EMAX  600000
#define GMAX  64

// ---------------- device scratch (zero at module load; re-zeroed by trailing
// kernel each replay so every invocation sees identical state) ----------------
__device__ float g_x1[NMAX * D];
__device__ float g_x2[NMAX * D];
__device__ float g_ns[NMAX];          // accumulates out-degree, then rsqrt-norm
__device__ float g_nd[NMAX];          // accumulates in-degree,  then rsqrt-norm
__device__ float g_gsum[GMAX * D];    // pooled sums (RED target)
__device__ int   g_row_start[NMAX + 1];
__device__ int   g_cursor[NMAX];
__device__ int   g_col[EMAX];

// ---------------- helpers ----------------------------------------------------
__device__ __forceinline__ void redv4(float* p, float4 v) {
    asm volatile(
        "{\n\t"
        ".reg .u64 gp;\n\t"
        "cvta.to.global.u64 gp, %0;\n\t"
        "red.global.add.v4.f32 [gp], {%1, %2, %3, %4};\n\t"
        "}"
        :: "l"(p), "f"(v.x), "f"(v.y), "f"(v.z), "f"(v.w)
        : "memory");
}

__device__ __forceinline__ unsigned long long pack2(float lo, float hi) {
    unsigned long long r;
    asm("mov.b64 %0, {%1, %2};" : "=l"(r) : "f"(lo), "f"(hi));
    return r;
}
__device__ __forceinline__ void unpack2(unsigned long long p, float& lo, float& hi) {
    asm("mov.b64 {%0, %1}, %2;" : "=f"(lo), "=f"(hi) : "l"(p));
}
__device__ __forceinline__ void ffma2(unsigned long long& acc,
                                      unsigned long long a, unsigned long long b) {
    asm("fma.rn.f32x2 %0, %1, %2, %0;" : "+l"(acc) : "l"(a), "l"(b));
}

// ---------------- stage 1: degree histograms (into pre-zeroed ns/nd) ---------
__global__ void k_degree(const int* __restrict__ src,
                         const int* __restrict__ dst,
                         float* __restrict__ ds, float* __restrict__ dd, int E) {
    int e = blockIdx.x * blockDim.x + threadIdx.x;
    if (e < E) {
        atomicAdd(&ds[src[e]], 1.0f);
        atomicAdd(&dd[dst[e]], 1.0f);
    }
}

// ---------------- stage 2: row_start scan + cursor + norms (one kernel) ------
// Block b: brute-force sum of all degrees in [0, b*256) (redundant but tiny),
// then Hillis-Steele local scan of its 256 degrees, then in-place rsqrt norms.
__global__ __launch_bounds__(256)
void k_rowstart_norm(float* __restrict__ ns, float* __restrict__ nd,
                     int* __restrict__ row_start, int* __restrict__ cursor,
                     int N, int E) {
    __shared__ int s[256];
    int tid = threadIdx.x;
    int base0 = blockIdx.x * 256;

    // global base = sum of degrees before this chunk
    int acc = 0;
    for (int i = tid; i < base0; i += 256) acc += (int)nd[i];
    s[tid] = acc;
    __syncthreads();
    for (int off = 128; off > 0; off >>= 1) {
        if (tid < off) s[tid] += s[tid + off];
        __syncthreads();
    }
    int base = s[0];
    __syncthreads();

    // local inclusive scan of this chunk's degrees
    int i = base0 + tid;
    int deg = (i < N) ? (int)nd[i] : 0;
    s[tid] = deg;
    __syncthreads();
    for (int off = 1; off < 256; off <<= 1) {
        int t = (tid >= off) ? s[tid - off] : 0;
        __syncthreads();
        s[tid] += t;
        __syncthreads();
    }

    if (i < N) {
        int rs = base + s[tid] - deg;   // exclusive
        row_start[i] = rs;
        cursor[i] = rs;
        if (i == N - 1) row_start[N] = E;
        ns[i] = rsqrtf(fmaxf(ns[i], 1.0f));
        nd[i] = rsqrtf(fmaxf(nd[i], 1.0f));
    }
}

// ---------------- stage 3: scatter edges into CSR ----------------------------
__global__ void k_fill(const int* __restrict__ src, const int* __restrict__ dst,
                       int* __restrict__ cursor, int* __restrict__ col, int E) {
    int e = blockIdx.x * blockDim.x + threadIdx.x;
    if (e < E) {
        int pos = atomicAdd(&cursor[dst[e]], 1);
        col[pos] = src[e];
    }
}

// ---------------- fused SpMM-gather + GEMM (launch #4 => ncu captures L1) ----
// y = relu((segment_sum(x[src]*ns[src] by dst) * nd[:,None]) @ W + b)
// Block: 64 rows x 128 cols, 256 threads; thread = 8 rows x 4 cols.
template <bool POOL>
__global__ __launch_bounds__(256)
void k_layer(const float* __restrict__ xin,
             const int* __restrict__ row_start, const int* __restrict__ col,
             const float* __restrict__ ns, const float* __restrict__ nd,
             const float* __restrict__ W, const float* __restrict__ b,
             float* __restrict__ y,
             const int* __restrict__ gid, float* __restrict__ gsum, int N) {
    __shared__ float Xs[64][D];

    int tid  = threadIdx.x;
    int tx   = tid & 31;   // lane: cols tx*4 .. tx*4+3
    int ty   = tid >> 5;   // warp: rows ty*8 .. ty*8+7
    int row0 = blockIdx.x * 64;

    const float4* x4 = (const float4*)xin;

    // --- gather phase: CSR in-edge accumulate per row, 4-deep MLP ---
#pragma unroll
    for (int r = 0; r < 8; r++) {
        int rl  = ty * 8 + r;
        int row = row0 + rl;
        float4 a0 = make_float4(0.f, 0.f, 0.f, 0.f);
        float4 a1 = make_float4(0.f, 0.f, 0.f, 0.f);
        if (row < N) {
            int e0 = __ldg(&row_start[row]);
            int e1 = __ldg(&row_start[row + 1]);
            int e  = e0;
            for (; e + 3 < e1; e += 4) {
                int s0 = __ldg(&col[e]);
                int s1 = __ldg(&col[e + 1]);
                int s2 = __ldg(&col[e + 2]);
                int s3 = __ldg(&col[e + 3]);
                float c0 = __ldg(&ns[s0]);
                float c1 = __ldg(&ns[s1]);
                float c2 = __ldg(&ns[s2]);
                float c3 = __ldg(&ns[s3]);
                float4 v0 = __ldg(&x4[(size_t)s0 * 32 + tx]);
                float4 v1 = __ldg(&x4[(size_t)s1 * 32 + tx]);
                float4 v2 = __ldg(&x4[(size_t)s2 * 32 + tx]);
                float4 v3 = __ldg(&x4[(size_t)s3 * 32 + tx]);
                a0.x += v0.x * c0; a0.y += v0.y * c0; a0.z += v0.z * c0; a0.w += v0.w * c0;
                a1.x += v1.x * c1; a1.y += v1.y * c1; a1.z += v1.z * c1; a1.w += v1.w * c1;
                a0.x += v2.x * c2; a0.y += v2.y * c2; a0.z += v2.z * c2; a0.w += v2.w * c2;
                a1.x += v3.x * c3; a1.y += v3.y * c3; a1.z += v3.z * c3; a1.w += v3.w * c3;
            }
            for (; e < e1; e++) {
                int s0 = __ldg(&col[e]);
                float c0 = __ldg(&ns[s0]);
                float4 v0 = __ldg(&x4[(size_t)s0 * 32 + tx]);
                a0.x += v0.x * c0; a0.y += v0.y * c0; a0.z += v0.z * c0; a0.w += v0.w * c0;
            }
            float s = __ldg(&nd[row]);
            a0.x = (a0.x + a1.x) * s;
            a0.y = (a0.y + a1.y) * s;
            a0.z = (a0.z + a1.z) * s;
            a0.w = (a0.w + a1.w) * s;
        }
        *(float4*)&Xs[rl][tx * 4] = a0;
    }
    __syncthreads();

    // --- GEMM phase ---
    unsigned long long acc[8][2];
#pragma unroll
    for (int r = 0; r < 8; r++) { acc[r][0] = 0ull; acc[r][1] = 0ull; }

    const float4* W4 = (const float4*)W;
#pragma unroll 4
    for (int k = 0; k < 128; k++) {
        float4 w = __ldg(&W4[k * 32 + tx]);
        unsigned long long w01 = pack2(w.x, w.y);
        unsigned long long w23 = pack2(w.z, w.w);
#pragma unroll
        for (int r = 0; r < 8; r++) {
            float xv = Xs[ty * 8 + r][k];    // warp-uniform broadcast LDS
            unsigned long long xx = pack2(xv, xv);
            ffma2(acc[r][0], xx, w01);
            ffma2(acc[r][1], xx, w23);
        }
    }

    float4 bb = __ldg(((const float4*)b) + tx);

    if (!POOL) {
#pragma unroll
        for (int r = 0; r < 8; r++) {
            int row = row0 + ty * 8 + r;
            if (row < N) {
                float o0, o1, o2, o3;
                unpack2(acc[r][0], o0, o1);
                unpack2(acc[r][1], o2, o3);
                float4 o = make_float4(fmaxf(o0 + bb.x, 0.f), fmaxf(o1 + bb.y, 0.f),
                                       fmaxf(o2 + bb.z, 0.f), fmaxf(o3 + bb.w, 0.f));
                *(float4*)(y + (size_t)row * D + tx * 4) = o;
            }
        }
    } else {
        // fused per-graph sum: graph_ids sorted -> flush-on-change
        int cur = -1;
        float4 s4 = make_float4(0.f, 0.f, 0.f, 0.f);
#pragma unroll
        for (int r = 0; r < 8; r++) {
            int row = row0 + ty * 8 + r;
            if (row >= N) break;
            float o0, o1, o2, o3;
            unpack2(acc[r][0], o0, o1);
            unpack2(acc[r][1], o2, o3);
            float4 o = make_float4(fmaxf(o0 + bb.x, 0.f), fmaxf(o1 + bb.y, 0.f),
                                   fmaxf(o2 + bb.z, 0.f), fmaxf(o3 + bb.w, 0.f));
            int g = __ldg(&gid[row]);
            if (g != cur) {
                if (cur >= 0) redv4(gsum + (size_t)cur * D + tx * 4, s4);
                cur = g;
                s4 = o;
            } else {
                s4.x += o.x; s4.y += o.y; s4.z += o.z; s4.w += o.w;
            }
        }
        if (cur >= 0) redv4(gsum + (size_t)cur * D + tx * 4, s4);
    }
}

// ---------------- final: mean = gsum / count (binary search, no atomics) -----
__global__ void k_final(const float* __restrict__ gsum, const int* __restrict__ gid,
                        float* __restrict__ out, int N) {
    int i = blockIdx.x * blockDim.x + threadIdx.x;
    if (i >= GMAX * D) return;
    int g = i >> 7;
    int lo = 0, hi = N;
    while (lo < hi) { int m = (lo + hi) >> 1; if (gid[m] < g) lo = m + 1; else hi = m; }
    int lb = lo;
    lo = 0; hi = N;
    while (lo < hi) { int m = (lo + hi) >> 1; if (gid[m] <= g) lo = m + 1; else hi = m; }
    float c = (float)(lo - lb);
    out[i] = gsum[i] / fmaxf(c, 1.0f);
}

// ---------------- trailing re-init for next replay ---------------------------
__global__ void k_reinit(float* __restrict__ ns, float* __restrict__ nd,
                         float* __restrict__ gsum, int N) {
    int i = blockIdx.x * blockDim.x + threadIdx.x;
    int stride = gridDim.x * blockDim.x;
    for (int j = i; j < N; j += stride) { ns[j] = 0.0f; nd[j] = 0.0f; }
    for (int j = i; j < GMAX * D; j += stride) gsum[j] = 0.0f;
}

// ---------------- launch ------------------------------------------------------
extern "C" void kernel_launch(void* const* d_in, const int* in_sizes, int n_in,
                              void* d_out, int out_size) {
    const float* h   = (const float*)d_in[0];
    const int*   src = (const int*)d_in[1];   // int32 (JAX x64 disabled)
    const int*   dst = (const int*)d_in[2];
    const int*   gid = (const int*)d_in[3];
    const float* W1 = (const float*)d_in[4];
    const float* b1 = (const float*)d_in[5];
    const float* W2 = (const float*)d_in[6];
    const float* b2 = (const float*)d_in[7];
    const float* W3 = (const float*)d_in[8];
    const float* b3 = (const float*)d_in[9];

    int N = in_sizes[0] / D;
    int E = in_sizes[1];
    float* out = (float*)d_out;

    float *x1, *x2, *ns, *nd, *gsum;
    int *row_start, *cursor, *col;
    cudaGetSymbolAddress((void**)&x1,   g_x1);
    cudaGetSymbolAddress((void**)&x2,   g_x2);
    cudaGetSymbolAddress((void**)&ns,   g_ns);
    cudaGetSymbolAddress((void**)&nd,   g_nd);
    cudaGetSymbolAddress((void**)&gsum, g_gsum);
    cudaGetSymbolAddress((void**)&row_start, g_row_start);
    cudaGetSymbolAddress((void**)&cursor,    g_cursor);
    cudaGetSymbolAddress((void**)&col,       g_col);

    int gemmBlocks = (N + 63) / 64;

    // #1: degrees (ns/nd are zero: module-load init or trailing reinit)
    k_degree<<<(E + 255) / 256, 256>>>(src, dst, ns, nd, E);
    // #2: row_start + cursor + norms
    k_rowstart_norm<<<(N + 255) / 256, 256>>>(ns, nd, row_start, cursor, N, E);
    // #3: CSR fill
    k_fill<<<(E + 255) / 256, 256>>>(src, dst, cursor, col, E);
    // #4: layer 1 (ncu capture slot)
    k_layer<false><<<gemmBlocks, 256>>>(h, row_start, col, ns, nd, W1, b1, x1,
                                        nullptr, nullptr, N);
    // #5: layer 2
    k_layer<false><<<gemmBlocks, 256>>>(x1, row_start, col, ns, nd, W2, b2, x2,
                                        nullptr, nullptr, N);
    // #6: layer 3 -> pooled sums into gsum
    k_layer<true><<<gemmBlocks, 256>>>(x2, row_start, col, ns, nd, W3, b3, nullptr,
                                       gid, gsum, N);
    // #7: mean via binary search on sorted gid
    k_final<<<(GMAX * D + 255) / 256, 256>>>(gsum, gid, out, N);
    // #8: re-zero accumulators for the next replay
    k_reinit<<<128, 256>>>(ns, nd, gsum, N);
}

// round 5
// speedup vs baseline: 1.6694x; 1.5605x over previous
#include <cuda_runtime.h>

#define D     128
#define NMAX  50000
#define EMAX  600000
#define GMAX  64

// ---------------- device scratch (zero at module load; re-zeroed by trailing
// kernel each replay so every invocation sees identical state) ----------------
__device__ float g_x1[NMAX * D];
__device__ float g_x2[NMAX * D];
__device__ float g_z [NMAX * D];      // Z = (X @ W) * ns
__device__ float g_ns[NMAX];          // accumulates out-degree, then rsqrt-norm
__device__ float g_nd[NMAX];          // accumulates in-degree,  then rsqrt-norm
__device__ float g_gsum[GMAX * D];    // pooled sums (RED target)
__device__ int   g_row_start[NMAX + 1];
__device__ int   g_cursor[NMAX];
__device__ int   g_col[EMAX];

// ---------------- helpers ----------------------------------------------------
__device__ __forceinline__ void redv4(float* p, float4 v) {
    asm volatile(
        "{\n\t"
        ".reg .u64 gp;\n\t"
        "cvta.to.global.u64 gp, %0;\n\t"
        "red.global.add.v4.f32 [gp], {%1, %2, %3, %4};\n\t"
        "}"
        :: "l"(p), "f"(v.x), "f"(v.y), "f"(v.z), "f"(v.w)
        : "memory");
}

__device__ __forceinline__ unsigned long long pack2(float lo, float hi) {
    unsigned long long r;
    asm("mov.b64 %0, {%1, %2};" : "=l"(r) : "f"(lo), "f"(hi));
    return r;
}
__device__ __forceinline__ void unpack2(unsigned long long p, float& lo, float& hi) {
    asm("mov.b64 {%0, %1}, %2;" : "=f"(lo), "=f"(hi) : "l"(p));
}
__device__ __forceinline__ void ffma2(unsigned long long& acc,
                                      unsigned long long a, unsigned long long b) {
    asm("fma.rn.f32x2 %0, %1, %2, %0;" : "+l"(acc) : "l"(a), "l"(b));
}

// ---------------- stage 1: degree histograms (into pre-zeroed ns/nd) ---------
__global__ void k_degree(const int* __restrict__ src,
                         const int* __restrict__ dst,
                         float* __restrict__ ds, float* __restrict__ dd, int E) {
    int e = blockIdx.x * blockDim.x + threadIdx.x;
    if (e < E) {
        atomicAdd(&ds[src[e]], 1.0f);
        atomicAdd(&dd[dst[e]], 1.0f);
    }
}

// ---------------- stage 2: row_start scan + cursor + norms (one kernel) ------
__global__ __launch_bounds__(256)
void k_rowstart_norm(float* __restrict__ ns, float* __restrict__ nd,
                     int* __restrict__ row_start, int* __restrict__ cursor,
                     int N, int E) {
    __shared__ int s[256];
    int tid = threadIdx.x;
    int base0 = blockIdx.x * 256;

    // global base = sum of in-degrees before this chunk (redundant brute force)
    int acc = 0;
    for (int i = tid; i < base0; i += 256) acc += (int)nd[i];
    s[tid] = acc;
    __syncthreads();
    for (int off = 128; off > 0; off >>= 1) {
        if (tid < off) s[tid] += s[tid + off];
        __syncthreads();
    }
    int base = s[0];
    __syncthreads();

    // local inclusive scan of this chunk's degrees
    int i = base0 + tid;
    int deg = (i < N) ? (int)nd[i] : 0;
    s[tid] = deg;
    __syncthreads();
    for (int off = 1; off < 256; off <<= 1) {
        int t = (tid >= off) ? s[tid - off] : 0;
        __syncthreads();
        s[tid] += t;
        __syncthreads();
    }

    if (i < N) {
        int rs = base + s[tid] - deg;   // exclusive
        row_start[i] = rs;
        cursor[i] = rs;
        if (i == N - 1) row_start[N] = E;
        ns[i] = rsqrtf(fmaxf(ns[i], 1.0f));
        nd[i] = rsqrtf(fmaxf(nd[i], 1.0f));
    }
}

// ---------------- stage 3: scatter edges into CSR ----------------------------
__global__ void k_fill(const int* __restrict__ src, const int* __restrict__ dst,
                       int* __restrict__ cursor, int* __restrict__ col, int E) {
    int e = blockIdx.x * blockDim.x + threadIdx.x;
    if (e < E) {
        int pos = atomicAdd(&cursor[dst[e]], 1);
        col[pos] = src[e];
    }
}

// ---------------- dense GEMM: Z = (X @ W) * ns[:,None] -----------------------
// Block: 64 rows x 128 cols, 256 threads; thread = 8 rows x 4 cols.
// k-loop vectorized: one LDS.128 per row per 4 k-steps.
__global__ __launch_bounds__(256)
void k_gemm(const float* __restrict__ X, const float* __restrict__ W,
            const float* __restrict__ ns, float* __restrict__ Z, int N) {
    __shared__ float Xs[64][D];

    int tid  = threadIdx.x;
    int tx   = tid & 31;   // cols tx*4 .. tx*4+3
    int ty   = tid >> 5;   // rows ty*8 .. ty*8+7
    int row0 = blockIdx.x * 64;

    const float4* x4 = (const float4*)X;
#pragma unroll
    for (int it = 0; it < 8; it++) {
        int slot = tid + it * 256;
        int rl = slot >> 5, c4 = slot & 31;
        int row = row0 + rl;
        float4 v = make_float4(0.f, 0.f, 0.f, 0.f);
        if (row < N) v = x4[(size_t)row * 32 + c4];
        *(float4*)&Xs[rl][c4 * 4] = v;
    }
    __syncthreads();

    unsigned long long acc[8][2];
#pragma unroll
    for (int r = 0; r < 8; r++) { acc[r][0] = 0ull; acc[r][1] = 0ull; }

    const float4* W4 = (const float4*)W;
#pragma unroll 2
    for (int k4 = 0; k4 < 32; k4++) {
        float4 xr[8];
#pragma unroll
        for (int r = 0; r < 8; r++)
            xr[r] = *(const float4*)&Xs[ty * 8 + r][k4 * 4];   // LDS.128 broadcast
#pragma unroll
        for (int kk = 0; kk < 4; kk++) {
            float4 w = __ldg(&W4[(k4 * 4 + kk) * 32 + tx]);
            unsigned long long w01 = pack2(w.x, w.y);
            unsigned long long w23 = pack2(w.z, w.w);
#pragma unroll
            for (int r = 0; r < 8; r++) {
                float xv = (&xr[r].x)[kk];
                unsigned long long xx = pack2(xv, xv);
                ffma2(acc[r][0], xx, w01);
                ffma2(acc[r][1], xx, w23);
            }
        }
    }

#pragma unroll
    for (int r = 0; r < 8; r++) {
        int row = row0 + ty * 8 + r;
        if (row < N) {
            float s = __ldg(&ns[row]);
            float o0, o1, o2, o3;
            unpack2(acc[r][0], o0, o1);
            unpack2(acc[r][1], o2, o3);
            float4 o = make_float4(o0 * s, o1 * s, o2 * s, o3 * s);
            *(float4*)(Z + (size_t)row * D + tx * 4) = o;
        }
    }
}

// ---------------- gather: y = relu(nd * segsum(Z[src]) + b) ------------------
// Warp per destination row; no smem in hot loop; rows independent.
// POOL: block (8 sorted rows) merges in smem, then few vector REDs.
template <bool POOL>
__global__ __launch_bounds__(256)
void k_gather(const float* __restrict__ Z,
              const int* __restrict__ row_start, const int* __restrict__ col,
              const float* __restrict__ nd, const float* __restrict__ b,
              float* __restrict__ y,
              const int* __restrict__ gid, float* __restrict__ gsum, int N) {
    int tid  = threadIdx.x;
    int lane = tid & 31;
    int wid  = tid >> 5;                       // 0..7
    int row  = blockIdx.x * 8 + wid;

    const float4* z4 = (const float4*)Z;
    float4 a0 = make_float4(0.f, 0.f, 0.f, 0.f);
    float4 a1 = make_float4(0.f, 0.f, 0.f, 0.f);

    if (row < N) {
        int e0 = __ldg(&row_start[row]);
        int e1 = __ldg(&row_start[row + 1]);
        int e  = e0;
        for (; e + 3 < e1; e += 4) {
            int s0 = __ldg(&col[e]);
            int s1 = __ldg(&col[e + 1]);
            int s2 = __ldg(&col[e + 2]);
            int s3 = __ldg(&col[e + 3]);
            float4 v0 = __ldg(&z4[(size_t)s0 * 32 + lane]);
            float4 v1 = __ldg(&z4[(size_t)s1 * 32 + lane]);
            float4 v2 = __ldg(&z4[(size_t)s2 * 32 + lane]);
            float4 v3 = __ldg(&z4[(size_t)s3 * 32 + lane]);
            a0.x += v0.x; a0.y += v0.y; a0.z += v0.z; a0.w += v0.w;
            a1.x += v1.x; a1.y += v1.y; a1.z += v1.z; a1.w += v1.w;
            a0.x += v2.x; a0.y += v2.y; a0.z += v2.z; a0.w += v2.w;
            a1.x += v3.x; a1.y += v3.y; a1.z += v3.z; a1.w += v3.w;
        }
        for (; e < e1; e++) {
            int s0 = __ldg(&col[e]);
            float4 v0 = __ldg(&z4[(size_t)s0 * 32 + lane]);
            a0.x += v0.x; a0.y += v0.y; a0.z += v0.z; a0.w += v0.w;
        }
    }

    float s  = (row < N) ? __ldg(&nd[row]) : 0.f;
    float4 bb = __ldg(((const float4*)b) + lane);
    float4 o;
    o.x = fmaxf((a0.x + a1.x) * s + bb.x, 0.f);
    o.y = fmaxf((a0.y + a1.y) * s + bb.y, 0.f);
    o.z = fmaxf((a0.z + a1.z) * s + bb.z, 0.f);
    o.w = fmaxf((a0.w + a1.w) * s + bb.w, 0.f);

    if (!POOL) {
        if (row < N)
            *(float4*)(y + (size_t)row * D + lane * 4) = o;
    } else {
        __shared__ float4 so[8][32];
        __shared__ int    sg[8];
        so[wid][lane] = o;
        if (lane == 0) sg[wid] = (row < N) ? __ldg(&gid[row]) : -1;
        __syncthreads();
        if (wid == 0) {
            int cur = -1;
            float4 s4 = make_float4(0.f, 0.f, 0.f, 0.f);
#pragma unroll
            for (int r = 0; r < 8; r++) {
                int g = sg[r];
                if (g < 0) break;
                float4 v = so[r][lane];
                if (g != cur) {
                    if (cur >= 0) redv4(gsum + (size_t)cur * D + lane * 4, s4);
                    cur = g;
                    s4 = v;
                } else {
                    s4.x += v.x; s4.y += v.y; s4.z += v.z; s4.w += v.w;
                }
            }
            if (cur >= 0) redv4(gsum + (size_t)cur * D + lane * 4, s4);
        }
    }
}

// ---------------- final: mean = gsum / count (binary search, no atomics) -----
__global__ void k_final(const float* __restrict__ gsum, const int* __restrict__ gid,
                        float* __restrict__ out, int N) {
    int i = blockIdx.x * blockDim.x + threadIdx.x;
    if (i >= GMAX * D) return;
    int g = i >> 7;
    int lo = 0, hi = N;
    while (lo < hi) { int m = (lo + hi) >> 1; if (gid[m] < g) lo = m + 1; else hi = m; }
    int lb = lo;
    lo = 0; hi = N;
    while (lo < hi) { int m = (lo + hi) >> 1; if (gid[m] <= g) lo = m + 1; else hi = m; }
    float c = (float)(lo - lb);
    out[i] = gsum[i] / fmaxf(c, 1.0f);
}

// ---------------- trailing re-init for next replay ---------------------------
__global__ void k_reinit(float* __restrict__ ns, float* __restrict__ nd,
                         float* __restrict__ gsum, int N) {
    int i = blockIdx.x * blockDim.x + threadIdx.x;
    int stride = gridDim.x * blockDim.x;
    for (int j = i; j < N; j += stride) { ns[j] = 0.0f; nd[j] = 0.0f; }
    for (int j = i; j < GMAX * D; j += stride) gsum[j] = 0.0f;
}

// ---------------- launch ------------------------------------------------------
extern "C" void kernel_launch(void* const* d_in, const int* in_sizes, int n_in,
                              void* d_out, int out_size) {
    const float* h   = (const float*)d_in[0];
    const int*   src = (const int*)d_in[1];   // int32 (JAX x64 disabled)
    const int*   dst = (const int*)d_in[2];
    const int*   gid = (const int*)d_in[3];
    const float* W1 = (const float*)d_in[4];
    const float* b1 = (const float*)d_in[5];
    const float* W2 = (const float*)d_in[6];
    const float* b2 = (const float*)d_in[7];
    const float* W3 = (const float*)d_in[8];
    const float* b3 = (const float*)d_in[9];

    int N = in_sizes[0] / D;
    int E = in_sizes[1];
    float* out = (float*)d_out;

    float *x1, *x2, *z, *ns, *nd, *gsum;
    int *row_start, *cursor, *col;
    cudaGetSymbolAddress((void**)&x1,   g_x1);
    cudaGetSymbolAddress((void**)&x2,   g_x2);
    cudaGetSymbolAddress((void**)&z,    g_z);
    cudaGetSymbolAddress((void**)&ns,   g_ns);
    cudaGetSymbolAddress((void**)&nd,   g_nd);
    cudaGetSymbolAddress((void**)&gsum, g_gsum);
    cudaGetSymbolAddress((void**)&row_start, g_row_start);
    cudaGetSymbolAddress((void**)&cursor,    g_cursor);
    cudaGetSymbolAddress((void**)&col,       g_col);

    int gemmBlocks   = (N + 63) / 64;
    int gatherBlocks = (N + 7) / 8;

    // #1..#3: CSR + norms
    k_degree<<<(E + 255) / 256, 256>>>(src, dst, ns, nd, E);
    k_rowstart_norm<<<(N + 255) / 256, 256>>>(ns, nd, row_start, cursor, N, E);
    k_fill<<<(E + 255) / 256, 256>>>(src, dst, cursor, col, E);

    // layer 1  (#4 = gemm -> ncu capture slot)
    k_gemm<<<gemmBlocks, 256>>>(h, W1, ns, z, N);
    k_gather<false><<<gatherBlocks, 256>>>(z, row_start, col, nd, b1, x1,
                                           nullptr, nullptr, N);
    // layer 2
    k_gemm<<<gemmBlocks, 256>>>(x1, W2, ns, z, N);
    k_gather<false><<<gatherBlocks, 256>>>(z, row_start, col, nd, b2, x2,
                                           nullptr, nullptr, N);
    // layer 3 -> pooled sums
    k_gemm<<<gemmBlocks, 256>>>(x2, W3, ns, z, N);
    k_gather<true><<<gatherBlocks, 256>>>(z, row_start, col, nd, b3, nullptr,
                                          gid, gsum, N);

    // mean + reinit
    k_final<<<(GMAX * D + 255) / 256, 256>>>(gsum, gid, out, N);
    k_reinit<<<128, 256>>>(ns, nd, gsum, N);
}

// round 6
// speedup vs baseline: 1.7986x; 1.0774x over previous
#include <cuda_runtime.h>

#define D     128
#define NMAX  50000
#define EMAX  600000
#define GMAX  64

// ---------------- device scratch (zero at module load; re-zeroed by trailing
// kernel each replay so every invocation sees identical state) ----------------
__device__ float g_x1[NMAX * D];
__device__ float g_x2[NMAX * D];
__device__ float g_z [NMAX * D];      // Z = (X @ W) * ns
__device__ float g_ns[NMAX];          // accumulates out-degree, then rsqrt-norm
__device__ float g_nd[NMAX];          // accumulates in-degree,  then rsqrt-norm
__device__ float g_gsum[GMAX * D];    // pooled sums (RED target)
__device__ int   g_row_start[NMAX + 1];
__device__ int   g_cursor[NMAX];
__device__ int   g_col[EMAX];

// ---------------- helpers ----------------------------------------------------
__device__ __forceinline__ void redv4(float* p, float4 v) {
    asm volatile(
        "{\n\t"
        ".reg .u64 gp;\n\t"
        "cvta.to.global.u64 gp, %0;\n\t"
        "red.global.add.v4.f32 [gp], {%1, %2, %3, %4};\n\t"
        "}"
        :: "l"(p), "f"(v.x), "f"(v.y), "f"(v.z), "f"(v.w)
        : "memory");
}

__device__ __forceinline__ unsigned long long pack2(float lo, float hi) {
    unsigned long long r;
    asm("mov.b64 %0, {%1, %2};" : "=l"(r) : "f"(lo), "f"(hi));
    return r;
}
__device__ __forceinline__ void unpack2(unsigned long long p, float& lo, float& hi) {
    asm("mov.b64 {%0, %1}, %2;" : "=f"(lo), "=f"(hi) : "l"(p));
}
__device__ __forceinline__ void ffma2(unsigned long long& acc,
                                      unsigned long long a, unsigned long long b) {
    asm("fma.rn.f32x2 %0, %1, %2, %0;" : "+l"(acc) : "l"(a), "l"(b));
}

// ---------------- stage 1: degree histograms (into pre-zeroed ns/nd) ---------
__global__ void k_degree(const int* __restrict__ src,
                         const int* __restrict__ dst,
                         float* __restrict__ ds, float* __restrict__ dd, int E) {
    int e = blockIdx.x * blockDim.x + threadIdx.x;
    if (e < E) {
        atomicAdd(&ds[src[e]], 1.0f);
        atomicAdd(&dd[dst[e]], 1.0f);
    }
}

// ---------------- stage 2: row_start scan + cursor + norms (one kernel) ------
__global__ __launch_bounds__(256)
void k_rowstart_norm(float* __restrict__ ns, float* __restrict__ nd,
                     int* __restrict__ row_start, int* __restrict__ cursor,
                     int N, int E) {
    __shared__ int s[256];
    int tid = threadIdx.x;
    int base0 = blockIdx.x * 256;

    // global base = sum of in-degrees before this chunk (redundant brute force)
    int acc = 0;
    for (int i = tid; i < base0; i += 256) acc += (int)nd[i];
    s[tid] = acc;
    __syncthreads();
    for (int off = 128; off > 0; off >>= 1) {
        if (tid < off) s[tid] += s[tid + off];
        __syncthreads();
    }
    int base = s[0];
    __syncthreads();

    // local inclusive scan of this chunk's degrees
    int i = base0 + tid;
    int deg = (i < N) ? (int)nd[i] : 0;
    s[tid] = deg;
    __syncthreads();
    for (int off = 1; off < 256; off <<= 1) {
        int t = (tid >= off) ? s[tid - off] : 0;
        __syncthreads();
        s[tid] += t;
        __syncthreads();
    }

    if (i < N) {
        int rs = base + s[tid] - deg;   // exclusive
        row_start[i] = rs;
        cursor[i] = rs;
        if (i == N - 1) row_start[N] = E;
        ns[i] = rsqrtf(fmaxf(ns[i], 1.0f));
        nd[i] = rsqrtf(fmaxf(nd[i], 1.0f));
    }
}

// ---------------- stage 3: scatter edges into CSR ----------------------------
__global__ void k_fill(const int* __restrict__ src, const int* __restrict__ dst,
                       int* __restrict__ cursor, int* __restrict__ col, int E) {
    int e = blockIdx.x * blockDim.x + threadIdx.x;
    if (e < E) {
        int pos = atomicAdd(&cursor[dst[e]], 1);
        col[pos] = src[e];
    }
}

// ---------------- dense GEMM: Z = (X @ W) * ns[:,None] -----------------------
// Tile 32 rows x 128 cols per block (256 thr); thread = 4 rows x 4 cols.
// Low reg footprint (acc 16 + xr 16) -> 4 blocks/SM -> fma-pipe saturation.
__global__ __launch_bounds__(256, 4)
void k_gemm(const float* __restrict__ X, const float* __restrict__ W,
            const float* __restrict__ ns, float* __restrict__ Z, int N) {
    __shared__ float Xs[32][D];

    int tid  = threadIdx.x;
    int tx   = tid & 31;   // cols tx*4 .. tx*4+3
    int ty   = tid >> 5;   // rows ty*4 .. ty*4+3
    int row0 = blockIdx.x * 32;

    const float4* x4 = (const float4*)X;
#pragma unroll
    for (int it = 0; it < 4; it++) {
        int slot = tid + it * 256;           // 0..1023
        int rl = slot >> 5, c4 = slot & 31;
        int row = row0 + rl;
        float4 v = make_float4(0.f, 0.f, 0.f, 0.f);
        if (row < N) v = x4[(size_t)row * 32 + c4];
        *(float4*)&Xs[rl][c4 * 4] = v;
    }
    __syncthreads();

    unsigned long long acc[4][2];
#pragma unroll
    for (int r = 0; r < 4; r++) { acc[r][0] = 0ull; acc[r][1] = 0ull; }

    const float4* W4 = (const float4*)W;
#pragma unroll 2
    for (int k4 = 0; k4 < 32; k4++) {
        float4 xr[4];
#pragma unroll
        for (int r = 0; r < 4; r++)
            xr[r] = *(const float4*)&Xs[ty * 4 + r][k4 * 4];   // LDS.128
#pragma unroll
        for (int kk = 0; kk < 4; kk++) {
            float4 w = __ldg(&W4[(k4 * 4 + kk) * 32 + tx]);
            unsigned long long w01 = pack2(w.x, w.y);
            unsigned long long w23 = pack2(w.z, w.w);
#pragma unroll
            for (int r = 0; r < 4; r++) {
                float xv = (&xr[r].x)[kk];
                unsigned long long xx = pack2(xv, xv);
                ffma2(acc[r][0], xx, w01);
                ffma2(acc[r][1], xx, w23);
            }
        }
    }

#pragma unroll
    for (int r = 0; r < 4; r++) {
        int row = row0 + ty * 4 + r;
        if (row < N) {
            float s = __ldg(&ns[row]);
            float o0, o1, o2, o3;
            unpack2(acc[r][0], o0, o1);
            unpack2(acc[r][1], o2, o3);
            float4 o = make_float4(o0 * s, o1 * s, o2 * s, o3 * s);
            *(float4*)(Z + (size_t)row * D + tx * 4) = o;
        }
    }
}

// ---------------- gather: y = relu(nd * segsum(Z[src]) + b) ------------------
// Warp per destination row; no smem in hot loop; rows independent.
// POOL: block (8 sorted rows) merges in smem, then few vector REDs.
template <bool POOL>
__global__ __launch_bounds__(256)
void k_gather(const float* __restrict__ Z,
              const int* __restrict__ row_start, const int* __restrict__ col,
              const float* __restrict__ nd, const float* __restrict__ b,
              float* __restrict__ y,
              const int* __restrict__ gid, float* __restrict__ gsum, int N) {
    int tid  = threadIdx.x;
    int lane = tid & 31;
    int wid  = tid >> 5;                       // 0..7
    int row  = blockIdx.x * 8 + wid;

    const float4* z4 = (const float4*)Z;
    float4 a0 = make_float4(0.f, 0.f, 0.f, 0.f);
    float4 a1 = make_float4(0.f, 0.f, 0.f, 0.f);

    if (row < N) {
        int e0 = __ldg(&row_start[row]);
        int e1 = __ldg(&row_start[row + 1]);
        int e  = e0;
        for (; e + 3 < e1; e += 4) {
            int s0 = __ldg(&col[e]);
            int s1 = __ldg(&col[e + 1]);
            int s2 = __ldg(&col[e + 2]);
            int s3 = __ldg(&col[e + 3]);
            float4 v0 = __ldg(&z4[(size_t)s0 * 32 + lane]);
            float4 v1 = __ldg(&z4[(size_t)s1 * 32 + lane]);
            float4 v2 = __ldg(&z4[(size_t)s2 * 32 + lane]);
            float4 v3 = __ldg(&z4[(size_t)s3 * 32 + lane]);
            a0.x += v0.x; a0.y += v0.y; a0.z += v0.z; a0.w += v0.w;
            a1.x += v1.x; a1.y += v1.y; a1.z += v1.z; a1.w += v1.w;
            a0.x += v2.x; a0.y += v2.y; a0.z += v2.z; a0.w += v2.w;
            a1.x += v3.x; a1.y += v3.y; a1.z += v3.z; a1.w += v3.w;
        }
        for (; e < e1; e++) {
            int s0 = __ldg(&col[e]);
            float4 v0 = __ldg(&z4[(size_t)s0 * 32 + lane]);
            a0.x += v0.x; a0.y += v0.y; a0.z += v0.z; a0.w += v0.w;
        }
    }

    float s  = (row < N) ? __ldg(&nd[row]) : 0.f;
    float4 bb = __ldg(((const float4*)b) + lane);
    float4 o;
    o.x = fmaxf((a0.x + a1.x) * s + bb.x, 0.f);
    o.y = fmaxf((a0.y + a1.y) * s + bb.y, 0.f);
    o.z = fmaxf((a0.z + a1.z) * s + bb.z, 0.f);
    o.w = fmaxf((a0.w + a1.w) * s + bb.w, 0.f);

    if (!POOL) {
        if (row < N)
            *(float4*)(y + (size_t)row * D + lane * 4) = o;
    } else {
        __shared__ float4 so[8][32];
        __shared__ int    sg[8];
        so[wid][lane] = o;
        if (lane == 0) sg[wid] = (row < N) ? __ldg(&gid[row]) : -1;
        __syncthreads();
        if (wid == 0) {
            int cur = -1;
            float4 s4 = make_float4(0.f, 0.f, 0.f, 0.f);
#pragma unroll
            for (int r = 0; r < 8; r++) {
                int g = sg[r];
                if (g < 0) break;
                float4 v = so[r][lane];
                if (g != cur) {
                    if (cur >= 0) redv4(gsum + (size_t)cur * D + lane * 4, s4);
                    cur = g;
                    s4 = v;
                } else {
                    s4.x += v.x; s4.y += v.y; s4.z += v.z; s4.w += v.w;
                }
            }
            if (cur >= 0) redv4(gsum + (size_t)cur * D + lane * 4, s4);
        }
    }
}

// ---------------- final: mean = gsum / count (binary search, no atomics) -----
__global__ void k_final(const float* __restrict__ gsum, const int* __restrict__ gid,
                        float* __restrict__ out, int N) {
    int i = blockIdx.x * blockDim.x + threadIdx.x;
    if (i >= GMAX * D) return;
    int g = i >> 7;
    int lo = 0, hi = N;
    while (lo < hi) { int m = (lo + hi) >> 1; if (gid[m] < g) lo = m + 1; else hi = m; }
    int lb = lo;
    lo = 0; hi = N;
    while (lo < hi) { int m = (lo + hi) >> 1; if (gid[m] <= g) lo = m + 1; else hi = m; }
    float c = (float)(lo - lb);
    out[i] = gsum[i] / fmaxf(c, 1.0f);
}

// ---------------- trailing re-init for next replay ---------------------------
__global__ void k_reinit(float* __restrict__ ns, float* __restrict__ nd,
                         float* __restrict__ gsum, int N) {
    int i = blockIdx.x * blockDim.x + threadIdx.x;
    int stride = gridDim.x * blockDim.x;
    for (int j = i; j < N; j += stride) { ns[j] = 0.0f; nd[j] = 0.0f; }
    for (int j = i; j < GMAX * D; j += stride) gsum[j] = 0.0f;
}

// ---------------- launch ------------------------------------------------------
extern "C" void kernel_launch(void* const* d_in, const int* in_sizes, int n_in,
                              void* d_out, int out_size) {
    const float* h   = (const float*)d_in[0];
    const int*   src = (const int*)d_in[1];   // int32 (JAX x64 disabled)
    const int*   dst = (const int*)d_in[2];
    const int*   gid = (const int*)d_in[3];
    const float* W1 = (const float*)d_in[4];
    const float* b1 = (const float*)d_in[5];
    const float* W2 = (const float*)d_in[6];
    const float* b2 = (const float*)d_in[7];
    const float* W3 = (const float*)d_in[8];
    const float* b3 = (const float*)d_in[9];

    int N = in_sizes[0] / D;
    int E = in_sizes[1];
    float* out = (float*)d_out;

    float *x1, *x2, *z, *ns, *nd, *gsum;
    int *row_start, *cursor, *col;
    cudaGetSymbolAddress((void**)&x1,   g_x1);
    cudaGetSymbolAddress((void**)&x2,   g_x2);
    cudaGetSymbolAddress((void**)&z,    g_z);
    cudaGetSymbolAddress((void**)&ns,   g_ns);
    cudaGetSymbolAddress((void**)&nd,   g_nd);
    cudaGetSymbolAddress((void**)&gsum, g_gsum);
    cudaGetSymbolAddress((void**)&row_start, g_row_start);
    cudaGetSymbolAddress((void**)&cursor,    g_cursor);
    cudaGetSymbolAddress((void**)&col,       g_col);

    int gemmBlocks   = (N + 31) / 32;
    int gatherBlocks = (N + 7) / 8;

    // #1..#3: CSR + norms
    k_degree<<<(E + 255) / 256, 256>>>(src, dst, ns, nd, E);
    k_rowstart_norm<<<(N + 255) / 256, 256>>>(ns, nd, row_start, cursor, N, E);
    k_fill<<<(E + 255) / 256, 256>>>(src, dst, cursor, col, E);

    // layer 1  (#4 = gemm -> ncu capture slot)
    k_gemm<<<gemmBlocks, 256>>>(h, W1, ns, z, N);
    k_gather<false><<<gatherBlocks, 256>>>(z, row_start, col, nd, b1, x1,
                                           nullptr, nullptr, N);
    // layer 2
    k_gemm<<<gemmBlocks, 256>>>(x1, W2, ns, z, N);
    k_gather<false><<<gatherBlocks, 256>>>(z, row_start, col, nd, b2, x2,
                                           nullptr, nullptr, N);
    // layer 3 -> pooled sums
    k_gemm<<<gemmBlocks, 256>>>(x2, W3, ns, z, N);
    k_gather<true><<<gatherBlocks, 256>>>(z, row_start, col, nd, b3, nullptr,
                                          gid, gsum, N);

    // mean + reinit
    k_final<<<(GMAX * D + 255) / 256, 256>>>(gsum, gid, out, N);
    k_reinit<<<128, 256>>>(ns, nd, gsum, N);
}

// round 7
// speedup vs baseline: 1.8289x; 1.0168x over previous
#include <cuda_runtime.h>

#define D     128
#define NMAX  50000
#define EMAX  600000
#define GMAX  64

// ---------------- device scratch (zero at module load; re-zeroed by trailing
// kernel each replay so every invocation sees identical state) ----------------
__device__ float g_x1[NMAX * D];
__device__ float g_x2[NMAX * D];
__device__ float g_z [NMAX * D];      // Z = (X @ W) * ns
__device__ float g_ns[NMAX];          // accumulates out-degree, then rsqrt-norm
__device__ float g_nd[NMAX];          // accumulates in-degree,  then rsqrt-norm
__device__ float g_gsum[GMAX * D];    // pooled sums (RED target)
__device__ int   g_row_start[NMAX + 1];
__device__ int   g_cursor[NMAX];
__device__ int   g_col[EMAX];

// ---------------- helpers ----------------------------------------------------
__device__ __forceinline__ void redv4(float* p, float4 v) {
    asm volatile(
        "{\n\t"
        ".reg .u64 gp;\n\t"
        "cvta.to.global.u64 gp, %0;\n\t"
        "red.global.add.v4.f32 [gp], {%1, %2, %3, %4};\n\t"
        "}"
        :: "l"(p), "f"(v.x), "f"(v.y), "f"(v.z), "f"(v.w)
        : "memory");
}

__device__ __forceinline__ unsigned long long pack2(float lo, float hi) {
    unsigned long long r;
    asm("mov.b64 %0, {%1, %2};" : "=l"(r) : "f"(lo), "f"(hi));
    return r;
}
__device__ __forceinline__ void unpack2(unsigned long long p, float& lo, float& hi) {
    asm("mov.b64 {%0, %1}, %2;" : "=f"(lo), "=f"(hi) : "l"(p));
}
__device__ __forceinline__ void ffma2(unsigned long long& acc,
                                      unsigned long long a, unsigned long long b) {
    asm("fma.rn.f32x2 %0, %1, %2, %0;" : "+l"(acc) : "l"(a), "l"(b));
}

// ---------------- stage 1: degree histograms (into pre-zeroed ns/nd) ---------
__global__ void k_degree(const int* __restrict__ src,
                         const int* __restrict__ dst,
                         float* __restrict__ ds, float* __restrict__ dd, int E) {
    int e = blockIdx.x * blockDim.x + threadIdx.x;
    if (e < E) {
        atomicAdd(&ds[src[e]], 1.0f);
        atomicAdd(&dd[dst[e]], 1.0f);
    }
}

// ---------------- stage 2: row_start scan + cursor + norms (one kernel) ------
__global__ __launch_bounds__(256)
void k_rowstart_norm(float* __restrict__ ns, float* __restrict__ nd,
                     int* __restrict__ row_start, int* __restrict__ cursor,
                     int N, int E) {
    __shared__ int s[256];
    int tid = threadIdx.x;
    int base0 = blockIdx.x * 256;

    // global base = sum of in-degrees before this chunk (redundant brute force)
    int acc = 0;
    for (int i = tid; i < base0; i += 256) acc += (int)nd[i];
    s[tid] = acc;
    __syncthreads();
    for (int off = 128; off > 0; off >>= 1) {
        if (tid < off) s[tid] += s[tid + off];
        __syncthreads();
    }
    int base = s[0];
    __syncthreads();

    // local inclusive scan of this chunk's degrees
    int i = base0 + tid;
    int deg = (i < N) ? (int)nd[i] : 0;
    s[tid] = deg;
    __syncthreads();
    for (int off = 1; off < 256; off <<= 1) {
        int t = (tid >= off) ? s[tid - off] : 0;
        __syncthreads();
        s[tid] += t;
        __syncthreads();
    }

    if (i < N) {
        int rs = base + s[tid] - deg;   // exclusive
        row_start[i] = rs;
        cursor[i] = rs;
        if (i == N - 1) row_start[N] = E;
        ns[i] = rsqrtf(fmaxf(ns[i], 1.0f));
        nd[i] = rsqrtf(fmaxf(nd[i], 1.0f));
    }
}

// ---------------- stage 3: scatter edges into CSR ----------------------------
__global__ void k_fill(const int* __restrict__ src, const int* __restrict__ dst,
                       int* __restrict__ cursor, int* __restrict__ col, int E) {
    int e = blockIdx.x * blockDim.x + threadIdx.x;
    if (e < E) {
        int pos = atomicAdd(&cursor[dst[e]], 1);
        col[pos] = src[e];
    }
}

// ---------------- dense GEMM: Z = (X @ W) * ns[:,None] -----------------------
// Tile 32 rows x 128 cols per block (256 thr); thread = 4 rows x 4 cols.
// Software-pipelined W stream: w for step k+1 is always in flight while the
// 8 FFMA2 of step k execute (breaks the LDG->FMA dependency chain).
__global__ __launch_bounds__(256, 3)
void k_gemm(const float* __restrict__ X, const float* __restrict__ W,
            const float* __restrict__ ns, float* __restrict__ Z, int N) {
    __shared__ float Xs[32][D];

    int tid  = threadIdx.x;
    int tx   = tid & 31;   // cols tx*4 .. tx*4+3
    int ty   = tid >> 5;   // rows ty*4 .. ty*4+3
    int row0 = blockIdx.x * 32;

    const float4* x4 = (const float4*)X;
#pragma unroll
    for (int it = 0; it < 4; it++) {
        int slot = tid + it * 256;           // 0..1023
        int rl = slot >> 5, c4 = slot & 31;
        int row = row0 + rl;
        float4 v = make_float4(0.f, 0.f, 0.f, 0.f);
        if (row < N) v = x4[(size_t)row * 32 + c4];
        *(float4*)&Xs[rl][c4 * 4] = v;
    }
    __syncthreads();

    unsigned long long acc[4][2];
#pragma unroll
    for (int r = 0; r < 4; r++) { acc[r][0] = 0ull; acc[r][1] = 0ull; }

    const float4* W4 = (const float4*)W;
    float4 w = __ldg(&W4[tx]);               // preload k = 0

#pragma unroll 2
    for (int k4 = 0; k4 < 32; k4++) {
        float4 xr[4];
#pragma unroll
        for (int r = 0; r < 4; r++)
            xr[r] = *(const float4*)&Xs[ty * 4 + r][k4 * 4];   // LDS.128 broadcast
#pragma unroll
        for (int kk = 0; kk < 4; kk++) {
            int kn = k4 * 4 + kk + 1;
            if (kn > 127) kn = 127;                            // clamped overshoot
            float4 wn = __ldg(&W4[kn * 32 + tx]);              // prefetch k+1
            unsigned long long w01 = pack2(w.x, w.y);
            unsigned long long w23 = pack2(w.z, w.w);
#pragma unroll
            for (int r = 0; r < 4; r++) {
                float xv = (&xr[r].x)[kk];
                unsigned long long xx = pack2(xv, xv);
                ffma2(acc[r][0], xx, w01);
                ffma2(acc[r][1], xx, w23);
            }
            w = wn;
        }
    }

#pragma unroll
    for (int r = 0; r < 4; r++) {
        int row = row0 + ty * 4 + r;
        if (row < N) {
            float s = __ldg(&ns[row]);
            float o0, o1, o2, o3;
            unpack2(acc[r][0], o0, o1);
            unpack2(acc[r][1], o2, o3);
            float4 o = make_float4(o0 * s, o1 * s, o2 * s, o3 * s);
            *(float4*)(Z + (size_t)row * D + tx * 4) = o;
        }
    }
}

// ---------------- gather: y = relu(nd * segsum(Z[src]) + b) ------------------
// Warp per destination row; no smem in hot loop; rows independent.
// POOL: block (8 sorted rows) merges in smem, then few vector REDs.
template <bool POOL>
__global__ __launch_bounds__(256)
void k_gather(const float* __restrict__ Z,
              const int* __restrict__ row_start, const int* __restrict__ col,
              const float* __restrict__ nd, const float* __restrict__ b,
              float* __restrict__ y,
              const int* __restrict__ gid, float* __restrict__ gsum, int N) {
    int tid  = threadIdx.x;
    int lane = tid & 31;
    int wid  = tid >> 5;                       // 0..7
    int row  = blockIdx.x * 8 + wid;

    const float4* z4 = (const float4*)Z;
    float4 a0 = make_float4(0.f, 0.f, 0.f, 0.f);
    float4 a1 = make_float4(0.f, 0.f, 0.f, 0.f);

    if (row < N) {
        int e0 = __ldg(&row_start[row]);
        int e1 = __ldg(&row_start[row + 1]);
        int e  = e0;
        for (; e + 3 < e1; e += 4) {
            int s0 = __ldg(&col[e]);
            int s1 = __ldg(&col[e + 1]);
            int s2 = __ldg(&col[e + 2]);
            int s3 = __ldg(&col[e + 3]);
            float4 v0 = __ldg(&z4[(size_t)s0 * 32 + lane]);
            float4 v1 = __ldg(&z4[(size_t)s1 * 32 + lane]);
            float4 v2 = __ldg(&z4[(size_t)s2 * 32 + lane]);
            float4 v3 = __ldg(&z4[(size_t)s3 * 32 + lane]);
            a0.x += v0.x; a0.y += v0.y; a0.z += v0.z; a0.w += v0.w;
            a1.x += v1.x; a1.y += v1.y; a1.z += v1.z; a1.w += v1.w;
            a0.x += v2.x; a0.y += v2.y; a0.z += v2.z; a0.w += v2.w;
            a1.x += v3.x; a1.y += v3.y; a1.z += v3.z; a1.w += v3.w;
        }
        for (; e < e1; e++) {
            int s0 = __ldg(&col[e]);
            float4 v0 = __ldg(&z4[(size_t)s0 * 32 + lane]);
            a0.x += v0.x; a0.y += v0.y; a0.z += v0.z; a0.w += v0.w;
        }
    }

    float s  = (row < N) ? __ldg(&nd[row]) : 0.f;
    float4 bb = __ldg(((const float4*)b) + lane);
    float4 o;
    o.x = fmaxf((a0.x + a1.x) * s + bb.x, 0.f);
    o.y = fmaxf((a0.y + a1.y) * s + bb.y, 0.f);
    o.z = fmaxf((a0.z + a1.z) * s + bb.z, 0.f);
    o.w = fmaxf((a0.w + a1.w) * s + bb.w, 0.f);

    if (!POOL) {
        if (row < N)
            *(float4*)(y + (size_t)row * D + lane * 4) = o;
    } else {
        __shared__ float4 so[8][32];
        __shared__ int    sg[8];
        so[wid][lane] = o;
        if (lane == 0) sg[wid] = (row < N) ? __ldg(&gid[row]) : -1;
        __syncthreads();
        if (wid == 0) {
            int cur = -1;
            float4 s4 = make_float4(0.f, 0.f, 0.f, 0.f);
#pragma unroll
            for (int r = 0; r < 8; r++) {
                int g = sg[r];
                if (g < 0) break;
                float4 v = so[r][lane];
                if (g != cur) {
                    if (cur >= 0) redv4(gsum + (size_t)cur * D + lane * 4, s4);
                    cur = g;
                    s4 = v;
                } else {
                    s4.x += v.x; s4.y += v.y; s4.z += v.z; s4.w += v.w;
                }
            }
            if (cur >= 0) redv4(gsum + (size_t)cur * D + lane * 4, s4);
        }
    }
}

// ---------------- final: mean = gsum / count (binary search, no atomics) -----
__global__ void k_final(const float* __restrict__ gsum, const int* __restrict__ gid,
                        float* __restrict__ out, int N) {
    int i = blockIdx.x * blockDim.x + threadIdx.x;
    if (i >= GMAX * D) return;
    int g = i >> 7;
    int lo = 0, hi = N;
    while (lo < hi) { int m = (lo + hi) >> 1; if (gid[m] < g) lo = m + 1; else hi = m; }
    int lb = lo;
    lo = 0; hi = N;
    while (lo < hi) { int m = (lo + hi) >> 1; if (gid[m] <= g) lo = m + 1; else hi = m; }
    float c = (float)(lo - lb);
    out[i] = gsum[i] / fmaxf(c, 1.0f);
}

// ---------------- trailing re-init for next replay ---------------------------
__global__ void k_reinit(float* __restrict__ ns, float* __restrict__ nd,
                         float* __restrict__ gsum, int N) {
    int i = blockIdx.x * blockDim.x + threadIdx.x;
    int stride = gridDim.x * blockDim.x;
    for (int j = i; j < N; j += stride) { ns[j] = 0.0f; nd[j] = 0.0f; }
    for (int j = i; j < GMAX * D; j += stride) gsum[j] = 0.0f;
}

// ---------------- launch ------------------------------------------------------
extern "C" void kernel_launch(void* const* d_in, const int* in_sizes, int n_in,
                              void* d_out, int out_size) {
    const float* h   = (const float*)d_in[0];
    const int*   src = (const int*)d_in[1];   // int32 (JAX x64 disabled)
    const int*   dst = (const int*)d_in[2];
    const int*   gid = (const int*)d_in[3];
    const float* W1 = (const float*)d_in[4];
    const float* b1 = (const float*)d_in[5];
    const float* W2 = (const float*)d_in[6];
    const float* b2 = (const float*)d_in[7];
    const float* W3 = (const float*)d_in[8];
    const float* b3 = (const float*)d_in[9];

    int N = in_sizes[0] / D;
    int E = in_sizes[1];
    float* out = (float*)d_out;

    float *x1, *x2, *z, *ns, *nd, *gsum;
    int *row_start, *cursor, *col;
    cudaGetSymbolAddress((void**)&x1,   g_x1);
    cudaGetSymbolAddress((void**)&x2,   g_x2);
    cudaGetSymbolAddress((void**)&z,    g_z);
    cudaGetSymbolAddress((void**)&ns,   g_ns);
    cudaGetSymbolAddress((void**)&nd,   g_nd);
    cudaGetSymbolAddress((void**)&gsum, g_gsum);
    cudaGetSymbolAddress((void**)&row_start, g_row_start);
    cudaGetSymbolAddress((void**)&cursor,    g_cursor);
    cudaGetSymbolAddress((void**)&col,       g_col);

    int gemmBlocks   = (N + 31) / 32;
    int gatherBlocks = (N + 7) / 8;

    // #1..#3: CSR + norms
    k_degree<<<(E + 255) / 256, 256>>>(src, dst, ns, nd, E);
    k_rowstart_norm<<<(N + 255) / 256, 256>>>(ns, nd, row_start, cursor, N, E);
    k_fill<<<(E + 255) / 256, 256>>>(src, dst, cursor, col, E);

    // layer 1  (#4 = gemm -> ncu capture slot)
    k_gemm<<<gemmBlocks, 256>>>(h, W1, ns, z, N);
    k_gather<false><<<gatherBlocks, 256>>>(z, row_start, col, nd, b1, x1,
                                           nullptr, nullptr, N);
    // layer 2
    k_gemm<<<gemmBlocks, 256>>>(x1, W2, ns, z, N);
    k_gather<false><<<gatherBlocks, 256>>>(z, row_start, col, nd, b2, x2,
                                           nullptr, nullptr, N);
    // layer 3 -> pooled sums
    k_gemm<<<gemmBlocks, 256>>>(x2, W3, ns, z, N);
    k_gather<true><<<gatherBlocks, 256>>>(z, row_start, col, nd, b3, nullptr,
                                          gid, gsum, N);

    // mean + reinit
    k_final<<<(GMAX * D + 255) / 256, 256>>>(gsum, gid, out, N);
    k_reinit<<<128, 256>>>(ns, nd, gsum, N);
}